// round 13
// baseline (speedup 1.0000x reference)
#include <cuda_runtime.h>
#include <cuda_fp16.h>
#include <cstdint>
#include <cstring>

#define DN 256
#define DP 128
#define LSEQ 512
#define BATCH 2
#define GRID 296

__device__ float g_a[BATCH * LSEQ * DP];
__device__ float g_b[BATCH * LSEQ * DP];
__device__ unsigned bar_cnt = 0;
__device__ volatile unsigned bar_gen = 0;

// ---------------------------------------------------------------------------
// helpers
// ---------------------------------------------------------------------------
__device__ __forceinline__ uint32_t pack_half2(float x, float y) {
    __half2 h = __floats2half2_rn(x, y);
    uint32_t u;
    memcpy(&u, &h, 4);
    return u;
}
__device__ __forceinline__ void mma16816(float* c, uint32_t a0, uint32_t a1,
                                         uint32_t a2, uint32_t a3,
                                         uint32_t b0, uint32_t b1) {
    asm volatile(
        "mma.sync.aligned.m16n8k16.row.col.f32.f16.f16.f32 "
        "{%0,%1,%2,%3}, {%4,%5,%6,%7}, {%8,%9}, {%0,%1,%2,%3};"
        : "+f"(c[0]), "+f"(c[1]), "+f"(c[2]), "+f"(c[3])
        : "r"(a0), "r"(a1), "r"(a2), "r"(a3), "r"(b0), "r"(b1));
}

// ---------------------------------------------------------------------------
// Fused kernel: phase A (LN + a/b projections) -> device barrier -> phase B
// 256 threads (8 warps), 2 CTAs/SM, 296 CTAs all co-resident.
// Phase B tile = 64 rows (8 i x 8 j) x 128 out, K = 128; fp32 swizzled Cs.
// ---------------------------------------------------------------------------
#define WS_STR 68   // phase-A weight stage stride (floats)
#define WSTR 136    // Wo_s row stride in halves
#define LSTR 136    // L_s row stride in halves
#define CSTR 136    // Cs row stride in floats (+ xor-16 swizzle on row bit2)
#define SM_WO   0                  // 128*136*2 = 34816
#define SM_L0   34816              // 64*136*2  = 17408
#define SM_L1   52224              // 17408
#define SM_C    69632              // 64*136*4  = 34816
#define SM_TOTAL 104448
#define NTILES  (BATCH * 64 * 64)  // 8192

__global__ __launch_bounds__(256, 2) void fused_kernel(
    const float* __restrict__ single, const float* __restrict__ pairp,
    const float* __restrict__ ng, const float* __restrict__ nb,
    const float* __restrict__ Wa, const float* __restrict__ ba,
    const float* __restrict__ Wb, const float* __restrict__ bb,
    const float* __restrict__ Wo, const float* __restrict__ bo,
    const float* __restrict__ pg, const float* __restrict__ pb,
    float* __restrict__ outp)
{
    extern __shared__ __align__(16) char smc[];
    int tid = threadIdx.x, wid = tid >> 5, lane = tid & 31;

    // ======================= Phase A: LN + projections ======================
    if (blockIdx.x < 256) {
        float* xn = (float*)smc;            // 4 x 256
        float* Ws = (float*)smc + 1024;     // 256 x 68
        int bid = blockIdx.x;

        if (wid < 4) {
            int grow = bid * 4 + wid;
            const float* x = single + grow * DN;
            float v[8], s = 0.f, sq = 0.f;
#pragma unroll
            for (int k = 0; k < 8; k++) { v[k] = x[lane + 32 * k]; s += v[k]; sq += v[k] * v[k]; }
#pragma unroll
            for (int o = 16; o > 0; o >>= 1) {
                s  += __shfl_xor_sync(0xFFFFFFFFu, s,  o);
                sq += __shfl_xor_sync(0xFFFFFFFFu, sq, o);
            }
            float mu = s * (1.f / DN);
            float rs = rsqrtf(sq * (1.f / DN) - mu * mu + 1e-5f);
#pragma unroll
            for (int k = 0; k < 8; k++) {
                int d = lane + 32 * k;
                xn[wid * DN + d] = (v[k] - mu) * rs * ng[d] + nb[d];
            }
        }
        __syncthreads();

        float acc[4] = {0.f, 0.f, 0.f, 0.f};
        int c = tid;
        for (int ch = 0; ch < 4; ch++) {
            int d0 = ch * 64;
            for (int e = tid; e < 16384; e += 256) {
                int cc = e >> 6, dc = e & 63;
                const float* src = (cc < DP) ? (Wa + cc * DN) : (Wb + (cc - DP) * DN);
                Ws[cc * WS_STR + dc] = src[d0 + dc];
            }
            __syncthreads();
#pragma unroll 2
            for (int dg = 0; dg < 16; dg++) {
                float4 w4 = *(const float4*)(Ws + c * WS_STR + dg * 4);
#pragma unroll
                for (int r = 0; r < 4; r++) {
                    float4 x4 = *(const float4*)(xn + r * DN + d0 + dg * 4);
                    acc[r] += w4.x * x4.x + w4.y * x4.y + w4.z * x4.z + w4.w * x4.w;
                }
            }
            __syncthreads();
        }
        int row0 = bid * 4;
        if (c < DP) {
            float bias = ba[c];
#pragma unroll
            for (int r = 0; r < 4; r++) g_a[(row0 + r) * DP + c] = acc[r] + bias;
        } else {
            float bias = bb[c - DP];
#pragma unroll
            for (int r = 0; r < 4; r++) g_b[(row0 + r) * DP + (c - DP)] = acc[r] + bias;
        }
    }
    __threadfence();
    __syncthreads();

    // ================= stage Wo (fp16) into smem ===========================
    __half* Wo_s = (__half*)(smc + SM_WO);
    float*  Cs   = (float*)(smc + SM_C);
    for (int e = tid; e < DP * 64; e += 256) {
        int n = e >> 6;
        int d = (e & 63) * 2;
        float2 w = *(const float2*)(Wo + n * DP + d);
        *(uint32_t*)(Wo_s + n * WSTR + d) = pack_half2(w.x, w.y);
    }
    float4 bo4 = *(const float4*)(bo + lane * 4);
    float4 pg4 = *(const float4*)(pg + lane * 4);
    float4 pb4 = *(const float4*)(pb + lane * 4);
    __syncthreads();

    // ======================= device-wide barrier ===========================
    if (tid == 0) {
        unsigned gen = bar_gen;
        __threadfence();
        if (atomicAdd(&bar_cnt, 1) == GRID - 1) {
            bar_cnt = 0;
            __threadfence();
            bar_gen = gen + 1;
        } else {
            while (bar_gen == gen) { }
        }
    }
    __syncthreads();
    __threadfence();

    // =========================== Phase B ===================================
    int wm = wid >> 2, wn = wid & 3;
    int g = lane >> 2, q = lane & 3;

    auto build = [&](int t, __half* Lb) {
        int bt  = t >> 12;
        int rem = t & 4095;
        int bi0 = (rem >> 6) * 8;
        int bj0 = (rem & 63) * 8;
        const float4 bv = ((const float4*)(g_b + (size_t)(bt * LSEQ + bj0 + wid) * DP))[lane];
#pragma unroll
        for (int r = 0; r < 8; r++) {
            float4 av = ((const float4*)(g_a + (size_t)(bt * LSEQ + bi0 + r) * DP))[lane];
            uint2 h;
            h.x = pack_half2(av.x * bv.x, av.y * bv.y);
            h.y = pack_half2(av.z * bv.z, av.w * bv.w);
            *(uint2*)(Lb + (wid * 8 + r) * LSTR + lane * 4) = h;
        }
    };

    int tile = blockIdx.x;
    if (tile < NTILES) build(tile, (__half*)(smc + SM_L0));
    __syncthreads();

    int p = 0;
    for (; tile < NTILES; tile += GRID) {
        int bt  = tile >> 12;
        int rem = tile & 4095;
        int i0  = (rem >> 6) * 8;
        int j0  = (rem & 63) * 8;
        __half* Lc = (__half*)(smc + (p ? SM_L1 : SM_L0));
        __half* Ln = (__half*)(smc + (p ? SM_L0 : SM_L1));

        // warp w epilogue rows m = w*8 + r  ->  gmem g0 + r*LSEQ*DP
        size_t g0 = (((size_t)(bt * LSEQ + i0)) * LSEQ + (j0 + wid)) * DP;

        // --- prefetch pair rows into regs (DRAM latency rides under MMA) ---
        float4 pv[8];
#pragma unroll
        for (int r = 0; r < 8; r++)
            pv[r] = *((const float4*)(pairp + g0 + (size_t)r * (LSEQ * DP)) + lane);

        // --- MMA: C[64x128] = L @ Wo^T, per-warp 32 rows x 32 cols ---
        float Cacc[2][4][4];
#pragma unroll
        for (int mt = 0; mt < 2; mt++)
#pragma unroll
            for (int nt = 0; nt < 4; nt++)
#pragma unroll
                for (int e = 0; e < 4; e++) Cacc[mt][nt][e] = 0.f;

#pragma unroll
        for (int ks = 0; ks < 8; ks++) {
            int k = ks * 16 + q * 2;
            uint32_t Bf[4][2];
#pragma unroll
            for (int nt = 0; nt < 4; nt++) {
                const __half* wr = Wo_s + (wn * 32 + nt * 8 + g) * WSTR + k;
                Bf[nt][0] = *(const uint32_t*)(wr);
                Bf[nt][1] = *(const uint32_t*)(wr + 8);
            }
#pragma unroll
            for (int mt = 0; mt < 2; mt++) {
                const __half* Ab = Lc + (wm * 32 + mt * 16 + g) * LSTR + k;
                uint32_t a0 = *(const uint32_t*)(Ab);
                uint32_t a1 = *(const uint32_t*)(Ab + 8 * LSTR);
                uint32_t a2 = *(const uint32_t*)(Ab + 8);
                uint32_t a3 = *(const uint32_t*)(Ab + 8 * LSTR + 8);
#pragma unroll
                for (int nt = 0; nt < 4; nt++)
                    mma16816(Cacc[mt][nt], a0, a1, a2, a3, Bf[nt][0], Bf[nt][1]);
            }
        }

        // --- stage C into Cs; xor-16 swizzle keyed on row bit2 (= g bit2) ---
#pragma unroll
        for (int mt = 0; mt < 2; mt++) {
            int r1 = wm * 32 + mt * 16 + g;
            int sw = (g & 4) << 2;
#pragma unroll
            for (int nt = 0; nt < 4; nt++) {
                int c0 = (wn * 32 + nt * 8 + q * 2) ^ sw;
                *(float2*)(Cs + r1 * CSTR + c0)       = make_float2(Cacc[mt][nt][0], Cacc[mt][nt][1]);
                *(float2*)(Cs + (r1 + 8) * CSTR + c0) = make_float2(Cacc[mt][nt][2], Cacc[mt][nt][3]);
            }
        }
        __syncthreads();   // Cs ready; Lc free

        // --- build next tile's L (overlaps epilogue) ---
        int nxt = tile + GRID;
        if (nxt < NTILES) build(nxt, Ln);

        // --- epilogue: warp w owns rows 8w..8w+7; full-row LN ---
        // Reading Cs at (lane*4 ^ sw_m) returns original cols lane*4..+3.
        const float rc = 1.f / 128.f;
#pragma unroll
        for (int r = 0; r < 8; r++) {
            int m = wid * 8 + r;
            int addr_col = (lane * 4) ^ ((m & 4) << 2);
            float4 cv = *(const float4*)(Cs + m * CSTR + addr_col);
            float v0 = cv.x + bo4.x + pv[r].x;
            float v1 = cv.y + bo4.y + pv[r].y;
            float v2 = cv.z + bo4.z + pv[r].z;
            float v3 = cv.w + bo4.w + pv[r].w;
            float s  = v0 + v1 + v2 + v3;
            float qq = v0 * v0 + v1 * v1 + v2 * v2 + v3 * v3;
#pragma unroll
            for (int o = 16; o > 0; o >>= 1) {
                s  += __shfl_xor_sync(0xFFFFFFFFu, s,  o);
                qq += __shfl_xor_sync(0xFFFFFFFFu, qq, o);
            }
            float mu = s * rc;
            float rstd = rsqrtf(qq * rc - mu * mu + 1e-5f);
            float4 ov;
            ov.x = (v0 - mu) * rstd * pg4.x + pb4.x;
            ov.y = (v1 - mu) * rstd * pg4.y + pb4.y;
            ov.z = (v2 - mu) * rstd * pg4.z + pb4.z;
            ov.w = (v3 - mu) * rstd * pg4.w + pb4.w;
            *((float4*)(outp + g0 + (size_t)r * (LSEQ * DP)) + lane) = ov;
        }
        __syncthreads();   // Ln ready for all warps; Cs free
        p ^= 1;
    }
}

// ---------------------------------------------------------------------------
// Host launcher — single kernel, single launch
// ---------------------------------------------------------------------------
extern "C" void kernel_launch(void* const* d_in, const int* in_sizes, int n_in,
                              void* d_out, int out_size)
{
    const float* single = (const float*)d_in[0];
    const float* pairp  = (const float*)d_in[1];
    const float* ng     = (const float*)d_in[2];
    const float* nb     = (const float*)d_in[3];
    const float* Wa     = (const float*)d_in[4];
    const float* ba     = (const float*)d_in[5];
    const float* Wb     = (const float*)d_in[6];
    const float* bb     = (const float*)d_in[7];
    const float* Wo     = (const float*)d_in[8];
    const float* bo     = (const float*)d_in[9];
    const float* pg     = (const float*)d_in[10];
    const float* pb     = (const float*)d_in[11];
    float* outp = (float*)d_out;

    cudaFuncSetAttribute(fused_kernel, cudaFuncAttributeMaxDynamicSharedMemorySize, SM_TOTAL);
    fused_kernel<<<GRID, 256, SM_TOTAL>>>(single, pairp, ng, nb, Wa, ba, Wb, bb,
                                          Wo, bo, pg, pb, outp);
}

// round 15
// speedup vs baseline: 1.1943x; 1.1943x over previous
#include <cuda_runtime.h>
#include <cuda_fp16.h>
#include <cstdint>
#include <cstring>

#define DN 256
#define DP 128
#define LSEQ 512
#define BATCH 2
#define GRID 148

__device__ float g_a[BATCH * LSEQ * DP];
__device__ float g_b[BATCH * LSEQ * DP];
__device__ unsigned bar_cnt = 0;
__device__ volatile unsigned bar_gen = 0;

// ---------------------------------------------------------------------------
// helpers
// ---------------------------------------------------------------------------
__device__ __forceinline__ uint32_t pack_half2(float x, float y) {
    __half2 h = __floats2half2_rn(x, y);
    uint32_t u;
    memcpy(&u, &h, 4);
    return u;
}
__device__ __forceinline__ void mma16816(float* c, uint32_t a0, uint32_t a1,
                                         uint32_t a2, uint32_t a3,
                                         uint32_t b0, uint32_t b1) {
    asm volatile(
        "mma.sync.aligned.m16n8k16.row.col.f32.f16.f16.f32 "
        "{%0,%1,%2,%3}, {%4,%5,%6,%7}, {%8,%9}, {%0,%1,%2,%3};"
        : "+f"(c[0]), "+f"(c[1]), "+f"(c[2]), "+f"(c[3])
        : "r"(a0), "r"(a1), "r"(a2), "r"(a3), "r"(b0), "r"(b1));
}

// ---------------------------------------------------------------------------
// Fused kernel: phase A (LN + a/b projections, CTAs 0-127) -> device barrier
// -> phase B (R6's 512-thread, 128-row-tile pipeline; best measured: 140.5us)
// 512 threads (16 warps), 1 CTA/SM, 148 CTAs all co-resident.
// ---------------------------------------------------------------------------
#define WS_STR 68   // phase-A weight stage stride (floats)
#define WSTR 136    // Wo_s row stride in halves
#define LSTR 136    // L_s row stride in halves
#define CSTR 136    // Cs row stride in floats
#define SM_WO   0                  // 128*136*2 = 34816
#define SM_L0   34816              // 128*136*2 = 34816
#define SM_L1   69632              // 34816
#define SM_C    104448             // 128*136*4 = 69632
#define SM_TOTAL 174080
#define NTILES  4096               // 2 batch * 64 i-tiles * 32 j-tiles

__global__ __launch_bounds__(512, 1) void fused_kernel(
    const float* __restrict__ single, const float* __restrict__ pairp,
    const float* __restrict__ ng, const float* __restrict__ nb,
    const float* __restrict__ Wa, const float* __restrict__ ba,
    const float* __restrict__ Wb, const float* __restrict__ bb,
    const float* __restrict__ Wo, const float* __restrict__ bo,
    const float* __restrict__ pg, const float* __restrict__ pb,
    float* __restrict__ outp)
{
    extern __shared__ __align__(16) char smc[];
    int tid = threadIdx.x, wid = tid >> 5, lane = tid & 31;

    // ======================= Phase A: LN + projections ======================
    // CTAs 0..127, 8 rows each; all 512 threads (c = tid&255, half = tid>>8)
    if (blockIdx.x < 128) {
        float* xn = (float*)smc;            // 8 x 256 (8KB)
        float* Ws = (float*)smc + 2048;     // 256 x 68 (69.6KB)
        int bid = blockIdx.x;

        if (wid < 8) {
            int grow = bid * 8 + wid;
            const float* x = single + grow * DN;
            float v[8], s = 0.f, sq = 0.f;
#pragma unroll
            for (int k = 0; k < 8; k++) { v[k] = x[lane + 32 * k]; s += v[k]; sq += v[k] * v[k]; }
#pragma unroll
            for (int o = 16; o > 0; o >>= 1) {
                s  += __shfl_xor_sync(0xFFFFFFFFu, s,  o);
                sq += __shfl_xor_sync(0xFFFFFFFFu, sq, o);
            }
            float mu = s * (1.f / DN);
            float rs = rsqrtf(sq * (1.f / DN) - mu * mu + 1e-5f);
#pragma unroll
            for (int k = 0; k < 8; k++) {
                int d = lane + 32 * k;
                xn[wid * DN + d] = (v[k] - mu) * rs * ng[d] + nb[d];
            }
        }
        __syncthreads();

        int c = tid & 255, half = tid >> 8;
        float acc[4] = {0.f, 0.f, 0.f, 0.f};
        for (int ch = 0; ch < 4; ch++) {
            int d0 = ch * 64;
            // stage W chunk as float4 (4096 float4s, 8 per thread)
            for (int e = tid; e < 4096; e += 512) {
                int cc = e >> 4, dq = e & 15;
                const float* src = (cc < DP) ? (Wa + cc * DN) : (Wb + (cc - DP) * DN);
                *(float4*)(Ws + cc * WS_STR + dq * 4) = *(const float4*)(src + d0 + dq * 4);
            }
            __syncthreads();
#pragma unroll 2
            for (int dg = 0; dg < 16; dg++) {
                float4 w4 = *(const float4*)(Ws + c * WS_STR + dg * 4);
#pragma unroll
                for (int r = 0; r < 4; r++) {
                    float4 x4 = *(const float4*)(xn + (half * 4 + r) * DN + d0 + dg * 4);
                    acc[r] += w4.x * x4.x + w4.y * x4.y + w4.z * x4.z + w4.w * x4.w;
                }
            }
            __syncthreads();
        }
        int row0 = bid * 8 + half * 4;
        if (c < DP) {
            float bias = ba[c];
#pragma unroll
            for (int r = 0; r < 4; r++) g_a[(row0 + r) * DP + c] = acc[r] + bias;
        } else {
            float bias = bb[c - DP];
#pragma unroll
            for (int r = 0; r < 4; r++) g_b[(row0 + r) * DP + (c - DP)] = acc[r] + bias;
        }
    }
    __threadfence();
    __syncthreads();

    // ================= stage Wo (fp16) into smem ===========================
    __half* Wo_s = (__half*)(smc + SM_WO);
    float*  Cs   = (float*)(smc + SM_C);
    for (int e = tid; e < DP * 64; e += 512) {
        int n = e >> 6;
        int d = (e & 63) * 2;
        float2 w = *(const float2*)(Wo + n * DP + d);
        *(uint32_t*)(Wo_s + n * WSTR + d) = pack_half2(w.x, w.y);
    }
    __syncthreads();

    // ======================= device-wide barrier ===========================
    if (tid == 0) {
        unsigned gen = bar_gen;
        __threadfence();
        if (atomicAdd(&bar_cnt, 1) == GRID - 1) {
            bar_cnt = 0;
            __threadfence();
            bar_gen = gen + 1;
        } else {
            while (bar_gen == gen) { }
        }
    }
    __syncthreads();
    __threadfence();

    // =========================== Phase B (R6) ==============================
    int wm = wid >> 2, wn = wid & 3;
    int g = lane >> 2, q = lane & 3;

    float4 bo4 = *(const float4*)(bo + lane * 4);
    float4 pg4 = *(const float4*)(pg + lane * 4);
    float4 pb4 = *(const float4*)(pb + lane * 4);

    // build L rows for a tile (warp w owns rows 8w..8w+7: jl = w, il = r)
    auto build = [&](int t, __half* Lb) {
        int bt  = t >> 11;
        int rem = t & 2047;
        int bi0 = (rem >> 5) * 8;
        int bj0 = (rem & 31) * 16;
        const float4 bv = ((const float4*)(g_b + (size_t)(bt * LSEQ + bj0 + wid) * DP))[lane];
#pragma unroll
        for (int r = 0; r < 8; r++) {
            float4 av = ((const float4*)(g_a + (size_t)(bt * LSEQ + bi0 + r) * DP))[lane];
            uint2 h;
            h.x = pack_half2(av.x * bv.x, av.y * bv.y);
            h.y = pack_half2(av.z * bv.z, av.w * bv.w);
            *(uint2*)(Lb + (wid * 8 + r) * LSTR + lane * 4) = h;
        }
    };

    int tile = blockIdx.x;
    if (tile < NTILES) build(tile, (__half*)(smc + SM_L0));
    __syncthreads();

    int p = 0;
    for (; tile < NTILES; tile += GRID) {
        int bt  = tile >> 11;
        int rem = tile & 2047;
        int i0  = (rem >> 5) * 8;
        int j0  = (rem & 31) * 16;
        __half* Lc = (__half*)(smc + (p ? SM_L1 : SM_L0));
        __half* Ln = (__half*)(smc + (p ? SM_L0 : SM_L1));

        // warp w epilogue rows m = w*8 + r -> gmem g0 + r*LSEQ*DP
        size_t g0 = (((size_t)(bt * LSEQ + i0)) * LSEQ + (j0 + wid)) * DP;

        // --- prefetch pair rows (DRAM latency rides under MMA) ---
        float4 pv[8];
#pragma unroll
        for (int r = 0; r < 8; r++)
            pv[r] = *((const float4*)(pairp + g0 + (size_t)r * (LSEQ * DP)) + lane);

        // --- MMA: C[128x128] = L @ Wo^T, per-warp 32 rows x 32 cols ---
        float Cacc[2][4][4];
#pragma unroll
        for (int mt = 0; mt < 2; mt++)
#pragma unroll
            for (int nt = 0; nt < 4; nt++)
#pragma unroll
                for (int e = 0; e < 4; e++) Cacc[mt][nt][e] = 0.f;

#pragma unroll
        for (int ks = 0; ks < 8; ks++) {
            int k = ks * 16 + q * 2;
            uint32_t Bf[4][2];
#pragma unroll
            for (int nt = 0; nt < 4; nt++) {
                const __half* wr = Wo_s + (wn * 32 + nt * 8 + g) * WSTR + k;
                Bf[nt][0] = *(const uint32_t*)(wr);
                Bf[nt][1] = *(const uint32_t*)(wr + 8);
            }
#pragma unroll
            for (int mt = 0; mt < 2; mt++) {
                const __half* Ab = Lc + (wm * 32 + mt * 16 + g) * LSTR + k;
                uint32_t a0 = *(const uint32_t*)(Ab);
                uint32_t a1 = *(const uint32_t*)(Ab + 8 * LSTR);
                uint32_t a2 = *(const uint32_t*)(Ab + 8);
                uint32_t a3 = *(const uint32_t*)(Ab + 8 * LSTR + 8);
#pragma unroll
                for (int nt = 0; nt < 4; nt++)
                    mma16816(Cacc[mt][nt], a0, a1, a2, a3, Bf[nt][0], Bf[nt][1]);
            }
        }

        // --- stage C fragments into Cs ---
#pragma unroll
        for (int mt = 0; mt < 2; mt++) {
            int r1 = wm * 32 + mt * 16 + g;
#pragma unroll
            for (int nt = 0; nt < 4; nt++) {
                int c0 = wn * 32 + nt * 8 + q * 2;
                *(float2*)(Cs + r1 * CSTR + c0)       = make_float2(Cacc[mt][nt][0], Cacc[mt][nt][1]);
                *(float2*)(Cs + (r1 + 8) * CSTR + c0) = make_float2(Cacc[mt][nt][2], Cacc[mt][nt][3]);
            }
        }
        __syncthreads();   // Cs visible; Lc free

        // --- build next tile's L (overlaps epilogue) ---
        int nxt = tile + GRID;
        if (nxt < NTILES) build(nxt, Ln);

        // --- epilogue: warp w owns rows 8w..8w+7; full-row LN ---
        const float rc = 1.f / 128.f;
#pragma unroll
        for (int r = 0; r < 8; r++) {
            int m = wid * 8 + r;
            float4 cv = *((const float4*)(Cs + m * CSTR) + lane);
            float v0 = cv.x + bo4.x + pv[r].x;
            float v1 = cv.y + bo4.y + pv[r].y;
            float v2 = cv.z + bo4.z + pv[r].z;
            float v3 = cv.w + bo4.w + pv[r].w;
            float s  = v0 + v1 + v2 + v3;
            float qq = v0 * v0 + v1 * v1 + v2 * v2 + v3 * v3;
#pragma unroll
            for (int o = 16; o > 0; o >>= 1) {
                s  += __shfl_xor_sync(0xFFFFFFFFu, s,  o);
                qq += __shfl_xor_sync(0xFFFFFFFFu, qq, o);
            }
            float mu = s * rc;
            float rstd = rsqrtf(qq * rc - mu * mu + 1e-5f);
            float4 ov;
            ov.x = (v0 - mu) * rstd * pg4.x + pb4.x;
            ov.y = (v1 - mu) * rstd * pg4.y + pb4.y;
            ov.z = (v2 - mu) * rstd * pg4.z + pb4.z;
            ov.w = (v3 - mu) * rstd * pg4.w + pb4.w;
            *((float4*)(outp + g0 + (size_t)r * (LSEQ * DP)) + lane) = ov;
        }
        __syncthreads();   // Ln ready for all warps; Cs free
        p ^= 1;
    }
}

// ---------------------------------------------------------------------------
// Host launcher — single kernel, single launch
// ---------------------------------------------------------------------------
extern "C" void kernel_launch(void* const* d_in, const int* in_sizes, int n_in,
                              void* d_out, int out_size)
{
    const float* single = (const float*)d_in[0];
    const float* pairp  = (const float*)d_in[1];
    const float* ng     = (const float*)d_in[2];
    const float* nb     = (const float*)d_in[3];
    const float* Wa     = (const float*)d_in[4];
    const float* ba     = (const float*)d_in[5];
    const float* Wb     = (const float*)d_in[6];
    const float* bb     = (const float*)d_in[7];
    const float* Wo     = (const float*)d_in[8];
    const float* bo     = (const float*)d_in[9];
    const float* pg     = (const float*)d_in[10];
    const float* pb     = (const float*)d_in[11];
    float* outp = (float*)d_out;

    cudaFuncSetAttribute(fused_kernel, cudaFuncAttributeMaxDynamicSharedMemorySize, SM_TOTAL);
    fused_kernel<<<GRID, 512, SM_TOTAL>>>(single, pairp, ng, nb, Wa, ba, Wb, bb,
                                          Wo, bo, pg, pb, outp);
}

// round 17
// speedup vs baseline: 1.2220x; 1.0232x over previous
#include <cuda_runtime.h>
#include <cuda_fp16.h>
#include <cstdint>
#include <cstring>

#define DN 256
#define DP 128
#define LSEQ 512
#define BATCH 2
#define GRID 148

__device__ float g_a[BATCH * LSEQ * DP];
__device__ float g_b[BATCH * LSEQ * DP];
__device__ unsigned bar_cnt = 0;
__device__ volatile unsigned bar_gen = 0;

// ---------------------------------------------------------------------------
// helpers
// ---------------------------------------------------------------------------
__device__ __forceinline__ uint32_t smem_u32(const void* p) {
    uint32_t a;
    asm("{ .reg .u64 t; cvta.to.shared.u64 t, %1; cvt.u32.u64 %0, t; }" : "=r"(a) : "l"(p));
    return a;
}
__device__ __forceinline__ uint32_t pack_half2(float x, float y) {
    __half2 h = __floats2half2_rn(x, y);
    uint32_t u;
    memcpy(&u, &h, 4);
    return u;
}
__device__ __forceinline__ void mma16816(float* c, uint32_t a0, uint32_t a1,
                                         uint32_t a2, uint32_t a3,
                                         uint32_t b0, uint32_t b1) {
    asm volatile(
        "mma.sync.aligned.m16n8k16.row.col.f32.f16.f16.f32 "
        "{%0,%1,%2,%3}, {%4,%5,%6,%7}, {%8,%9}, {%0,%1,%2,%3};"
        : "+f"(c[0]), "+f"(c[1]), "+f"(c[2]), "+f"(c[3])
        : "r"(a0), "r"(a1), "r"(a2), "r"(a3), "r"(b0), "r"(b1));
}
__device__ __forceinline__ void ldmatrix_x4(uint32_t& r0, uint32_t& r1,
                                            uint32_t& r2, uint32_t& r3,
                                            uint32_t addr) {
    asm volatile("ldmatrix.sync.aligned.m8n8.x4.shared.b16 {%0,%1,%2,%3}, [%4];"
                 : "=r"(r0), "=r"(r1), "=r"(r2), "=r"(r3) : "r"(addr));
}

// ---------------------------------------------------------------------------
// Fused kernel: phase A (LN + a/b projections, CTAs 0-127) -> device barrier
// -> phase B (512-thread, 128-row tile, ldmatrix fragment loads)
// ---------------------------------------------------------------------------
#define WS_STR 68   // phase-A weight stage stride (floats)
#define WSTR 136    // Wo_s row stride in halves
#define LSTR 136    // L_s row stride in halves
#define CSTR 136    // Cs row stride in floats
#define SM_WO   0                  // 128*136*2 = 34816
#define SM_L0   34816              // 128*136*2 = 34816
#define SM_L1   69632              // 34816
#define SM_C    104448             // 128*136*4 = 69632
#define SM_TOTAL 174080
#define NTILES  4096               // 2 batch * 64 i-tiles * 32 j-tiles

__global__ __launch_bounds__(512, 1) void fused_kernel(
    const float* __restrict__ single, const float* __restrict__ pairp,
    const float* __restrict__ ng, const float* __restrict__ nb,
    const float* __restrict__ Wa, const float* __restrict__ ba,
    const float* __restrict__ Wb, const float* __restrict__ bb,
    const float* __restrict__ Wo, const float* __restrict__ bo,
    const float* __restrict__ pg, const float* __restrict__ pb,
    float* __restrict__ outp)
{
    extern __shared__ __align__(16) char smc[];
    int tid = threadIdx.x, wid = tid >> 5, lane = tid & 31;

    // ======================= Phase A: LN + projections ======================
    if (blockIdx.x < 128) {
        float* xn = (float*)smc;            // 8 x 256
        float* Ws = (float*)smc + 2048;     // 256 x 68
        int bid = blockIdx.x;

        if (wid < 8) {
            int grow = bid * 8 + wid;
            const float* x = single + grow * DN;
            float v[8], s = 0.f, sq = 0.f;
#pragma unroll
            for (int k = 0; k < 8; k++) { v[k] = x[lane + 32 * k]; s += v[k]; sq += v[k] * v[k]; }
#pragma unroll
            for (int o = 16; o > 0; o >>= 1) {
                s  += __shfl_xor_sync(0xFFFFFFFFu, s,  o);
                sq += __shfl_xor_sync(0xFFFFFFFFu, sq, o);
            }
            float mu = s * (1.f / DN);
            float rs = rsqrtf(sq * (1.f / DN) - mu * mu + 1e-5f);
#pragma unroll
            for (int k = 0; k < 8; k++) {
                int d = lane + 32 * k;
                xn[wid * DN + d] = (v[k] - mu) * rs * ng[d] + nb[d];
            }
        }
        __syncthreads();

        int c = tid & 255, half = tid >> 8;
        float acc[4] = {0.f, 0.f, 0.f, 0.f};
        for (int ch = 0; ch < 4; ch++) {
            int d0 = ch * 64;
            for (int e = tid; e < 4096; e += 512) {
                int cc = e >> 4, dq = e & 15;
                const float* src = (cc < DP) ? (Wa + cc * DN) : (Wb + (cc - DP) * DN);
                *(float4*)(Ws + cc * WS_STR + dq * 4) = *(const float4*)(src + d0 + dq * 4);
            }
            __syncthreads();
#pragma unroll 2
            for (int dg = 0; dg < 16; dg++) {
                float4 w4 = *(const float4*)(Ws + c * WS_STR + dg * 4);
#pragma unroll
                for (int r = 0; r < 4; r++) {
                    float4 x4 = *(const float4*)(xn + (half * 4 + r) * DN + d0 + dg * 4);
                    acc[r] += w4.x * x4.x + w4.y * x4.y + w4.z * x4.z + w4.w * x4.w;
                }
            }
            __syncthreads();
        }
        int row0 = bid * 8 + half * 4;
        if (c < DP) {
            float bias = ba[c];
#pragma unroll
            for (int r = 0; r < 4; r++) g_a[(row0 + r) * DP + c] = acc[r] + bias;
        } else {
            float bias = bb[c - DP];
#pragma unroll
            for (int r = 0; r < 4; r++) g_b[(row0 + r) * DP + (c - DP)] = acc[r] + bias;
        }
    }
    __threadfence();
    __syncthreads();

    // ================= stage Wo (fp16) into smem ===========================
    __half* Wo_s = (__half*)(smc + SM_WO);
    float*  Cs   = (float*)(smc + SM_C);
    for (int e = tid; e < DP * 64; e += 512) {
        int n = e >> 6;
        int d = (e & 63) * 2;
        float2 w = *(const float2*)(Wo + n * DP + d);
        *(uint32_t*)(Wo_s + n * WSTR + d) = pack_half2(w.x, w.y);
    }
    __syncthreads();

    // ======================= device-wide barrier ===========================
    if (tid == 0) {
        unsigned gen = bar_gen;
        __threadfence();
        if (atomicAdd(&bar_cnt, 1) == GRID - 1) {
            bar_cnt = 0;
            __threadfence();
            bar_gen = gen + 1;
        } else {
            while (bar_gen == gen) { }
        }
    }
    __syncthreads();
    __threadfence();

    // =========================== Phase B ===================================
    int wm = wid >> 2, wn = wid & 3;
    int lr = lane & 7, lg = lane >> 3;

    float4 bo4 = *(const float4*)(bo + lane * 4);
    float4 pg4 = *(const float4*)(pg + lane * 4);
    float4 pb4 = *(const float4*)(pb + lane * 4);

    uint32_t sbase = smem_u32(smc);

    // ldmatrix lane addresses:
    // A (x4, mt tile): row = wm*32 + mt*16 + (lg&1)*8 + lr, col8 = (lg>>1)*8
    //   -> regs {a0,a1,a2,a3}
    uint32_t aOff[2];
#pragma unroll
    for (int mt = 0; mt < 2; mt++) {
        int row = wm * 32 + mt * 16 + ((lg & 1) << 3) + lr;
        aOff[mt] = (uint32_t)(row * LSTR + ((lg >> 1) << 3)) * 2u;
    }
    // B (x4, nt-pair tile): row = wn*32 + ntp*16 + (lg>>1)*8 + lr, col8 = (lg&1)*8
    //   -> regs {b(nt0,0), b(nt0,1), b(nt1,0), b(nt1,1)}
    uint32_t bAddr[2];
#pragma unroll
    for (int ntp = 0; ntp < 2; ntp++) {
        int row = wn * 32 + ntp * 16 + ((lg >> 1) << 3) + lr;
        bAddr[ntp] = sbase + SM_WO + (uint32_t)(row * WSTR + ((lg & 1) << 3)) * 2u;
    }

    int g = lane >> 2, q = lane & 3;

    // build L rows for a tile (warp w owns rows 8w..8w+7: jl = w, il = r)
    auto build = [&](int t, __half* Lb) {
        int bt  = t >> 11;
        int rem = t & 2047;
        int bi0 = (rem >> 5) * 8;
        int bj0 = (rem & 31) * 16;
        const float4 bv = ((const float4*)(g_b + (size_t)(bt * LSEQ + bj0 + wid) * DP))[lane];
#pragma unroll
        for (int r = 0; r < 8; r++) {
            float4 av = ((const float4*)(g_a + (size_t)(bt * LSEQ + bi0 + r) * DP))[lane];
            uint2 h;
            h.x = pack_half2(av.x * bv.x, av.y * bv.y);
            h.y = pack_half2(av.z * bv.z, av.w * bv.w);
            *(uint2*)(Lb + (wid * 8 + r) * LSTR + lane * 4) = h;
        }
    };

    int tile = blockIdx.x;
    if (tile < NTILES) build(tile, (__half*)(smc + SM_L0));
    __syncthreads();

    int p = 0;
    for (; tile < NTILES; tile += GRID) {
        int bt  = tile >> 11;
        int rem = tile & 2047;
        int i0  = (rem >> 5) * 8;
        int j0  = (rem & 31) * 16;
        __half* Lc = (__half*)(smc + (p ? SM_L1 : SM_L0));
        __half* Ln = (__half*)(smc + (p ? SM_L0 : SM_L1));
        uint32_t lcBase = sbase + (p ? SM_L1 : SM_L0);

        size_t g0 = (((size_t)(bt * LSEQ + i0)) * LSEQ + (j0 + wid)) * DP;

        // --- prefetch pair rows (DRAM latency rides under MMA) ---
        float4 pv[8];
#pragma unroll
        for (int r = 0; r < 8; r++)
            pv[r] = *((const float4*)(pairp + g0 + (size_t)r * (LSEQ * DP)) + lane);

        // --- MMA: C[128x128] = L @ Wo^T (ldmatrix fragment loads) ---
        float Cacc[2][4][4];
#pragma unroll
        for (int mt = 0; mt < 2; mt++)
#pragma unroll
            for (int nt = 0; nt < 4; nt++)
#pragma unroll
                for (int e = 0; e < 4; e++) Cacc[mt][nt][e] = 0.f;

#pragma unroll
        for (int ks = 0; ks < 8; ks++) {
            uint32_t koff = (uint32_t)ks * 32u;   // 16 halves
            uint32_t Bf[4][2];
            ldmatrix_x4(Bf[0][0], Bf[0][1], Bf[1][0], Bf[1][1], bAddr[0] + koff);
            ldmatrix_x4(Bf[2][0], Bf[2][1], Bf[3][0], Bf[3][1], bAddr[1] + koff);
#pragma unroll
            for (int mt = 0; mt < 2; mt++) {
                uint32_t a0, a1, a2, a3;
                ldmatrix_x4(a0, a1, a2, a3, lcBase + aOff[mt] + koff);
#pragma unroll
                for (int nt = 0; nt < 4; nt++)
                    mma16816(Cacc[mt][nt], a0, a1, a2, a3, Bf[nt][0], Bf[nt][1]);
            }
        }

        // --- stage C fragments into Cs ---
#pragma unroll
        for (int mt = 0; mt < 2; mt++) {
            int r1 = wm * 32 + mt * 16 + g;
#pragma unroll
            for (int nt = 0; nt < 4; nt++) {
                int c0 = wn * 32 + nt * 8 + q * 2;
                *(float2*)(Cs + r1 * CSTR + c0)       = make_float2(Cacc[mt][nt][0], Cacc[mt][nt][1]);
                *(float2*)(Cs + (r1 + 8) * CSTR + c0) = make_float2(Cacc[mt][nt][2], Cacc[mt][nt][3]);
            }
        }
        __syncthreads();   // Cs visible; Lc free

        // --- build next tile's L (overlaps epilogue) ---
        int nxt = tile + GRID;
        if (nxt < NTILES) build(nxt, Ln);

        // --- epilogue: warp w owns rows 8w..8w+7; full-row LN ---
        const float rc = 1.f / 128.f;
#pragma unroll
        for (int r = 0; r < 8; r++) {
            int m = wid * 8 + r;
            float4 cv = *((const float4*)(Cs + m * CSTR) + lane);
            float v0 = cv.x + bo4.x + pv[r].x;
            float v1 = cv.y + bo4.y + pv[r].y;
            float v2 = cv.z + bo4.z + pv[r].z;
            float v3 = cv.w + bo4.w + pv[r].w;
            float s  = v0 + v1 + v2 + v3;
            float qq = v0 * v0 + v1 * v1 + v2 * v2 + v3 * v3;
#pragma unroll
            for (int o = 16; o > 0; o >>= 1) {
                s  += __shfl_xor_sync(0xFFFFFFFFu, s,  o);
                qq += __shfl_xor_sync(0xFFFFFFFFu, qq, o);
            }
            float mu = s * rc;
            float rstd = rsqrtf(qq * rc - mu * mu + 1e-5f);
            float4 ov;
            ov.x = (v0 - mu) * rstd * pg4.x + pb4.x;
            ov.y = (v1 - mu) * rstd * pg4.y + pb4.y;
            ov.z = (v2 - mu) * rstd * pg4.z + pb4.z;
            ov.w = (v3 - mu) * rstd * pg4.w + pb4.w;
            *((float4*)(outp + g0 + (size_t)r * (LSEQ * DP)) + lane) = ov;
        }
        __syncthreads();   // Ln ready for all warps; Cs free
        p ^= 1;
    }
}

// ---------------------------------------------------------------------------
// Host launcher — single kernel, single launch
// ---------------------------------------------------------------------------
extern "C" void kernel_launch(void* const* d_in, const int* in_sizes, int n_in,
                              void* d_out, int out_size)
{
    const float* single = (const float*)d_in[0];
    const float* pairp  = (const float*)d_in[1];
    const float* ng     = (const float*)d_in[2];
    const float* nb     = (const float*)d_in[3];
    const float* Wa     = (const float*)d_in[4];
    const float* ba     = (const float*)d_in[5];
    const float* Wb     = (const float*)d_in[6];
    const float* bb     = (const float*)d_in[7];
    const float* Wo     = (const float*)d_in[8];
    const float* bo     = (const float*)d_in[9];
    const float* pg     = (const float*)d_in[10];
    const float* pb     = (const float*)d_in[11];
    float* outp = (float*)d_out;

    cudaFuncSetAttribute(fused_kernel, cudaFuncAttributeMaxDynamicSharedMemorySize, SM_TOTAL);
    fused_kernel<<<GRID, 512, SM_TOTAL>>>(single, pairp, ng, nb, Wa, ba, Wb, bb,
                                          Wo, bo, pg, pb, outp);
}